// round 17
// baseline (speedup 1.0000x reference)
#include <cuda_runtime.h>
#include <cuda_bf16.h>
#include <math_constants.h>
#include <cstdint>

// Problem constants
#define BB 4
#define SS 4096
#define EE 256
#define DD 32

// ---- bf16 mma.sync m16n8k16 (arch-generic PTX -> HMMA on sm_103) ----
__device__ __forceinline__ void mma_bf16(float c[4], const uint32_t a[4],
                                         uint32_t b0, uint32_t b1) {
    asm volatile(
        "mma.sync.aligned.m16n8k16.row.col.f32.bf16.bf16.f32 "
        "{%0,%1,%2,%3}, {%4,%5,%6,%7}, {%8,%9}, {%0,%1,%2,%3};"
        : "+f"(c[0]), "+f"(c[1]), "+f"(c[2]), "+f"(c[3])
        : "r"(a[0]), "r"(a[1]), "r"(a[2]), "r"(a[3]), "r"(b0), "r"(b1));
}
__device__ __forceinline__ void ldsm_x4(uint32_t& r0, uint32_t& r1,
                                        uint32_t& r2, uint32_t& r3, uint32_t addr) {
    asm volatile("ldmatrix.sync.aligned.m8n8.x4.shared.b16 {%0,%1,%2,%3}, [%4];"
        : "=r"(r0), "=r"(r1), "=r"(r2), "=r"(r3) : "r"(addr));
}
__device__ __forceinline__ uint32_t smem_u32(const void* p) {
    uint32_t a;
    asm("{ .reg .u64 t; cvta.to.shared.u64 t, %1; cvt.u32.u64 %0, t; }" : "=r"(a) : "l"(p));
    return a;
}
__device__ __forceinline__ uint32_t cvt_bf2(float a, float b) {
    uint32_t r;
    asm("cvt.rn.satfinite.bf16x2.f32 %0, %1, %2;" : "=r"(r) : "f"(b), "f"(a));
    return r;
}
__device__ __forceinline__ float ex2f(float x) {
    float y; asm("ex2.approx.f32 %0, %1;" : "=f"(y) : "f"(x)); return y;
}

// Device scratch.
__device__ __nv_bfloat16 g_qh[BB * SS * DD], g_ql[BB * SS * DD];
__device__ __nv_bfloat16 g_kh[BB * SS * DD], g_kl[BB * SS * DD];
__device__ uint32_t g_vph[BB * DD * SS / 2], g_vpl[BB * DD * SS / 2];
__device__ float g_pacc[2][BB * SS * DD];
__device__ float g_pl[2][BB * SS];
// Pre-split W in proj smem chunk order: [ch][split][n][we] (n = mat*32+d).
__device__ uint32_t g_ws[4 * 2 * 96 * 32];

// ---------------------------------------------------------------------------
// W split prep: done ONCE (was repeated by all 256 proj CTAs).
// idx -> we(32) | n(96) | ch(4); word = {W[e0][d], W[e0+1][d]} hi or lo split.
// ---------------------------------------------------------------------------
__global__ __launch_bounds__(256, 1) void wsplit_kernel(
    const float* __restrict__ Wq,
    const float* __restrict__ Wk,
    const float* __restrict__ Wv)
{
    const int idx = blockIdx.x * 256 + threadIdx.x;   // 0..12287
    const int we = idx & 31;
    const int n  = (idx >> 5) % 96;
    const int ch = (idx >> 5) / 96;
    const int mat = n >> 5, d = n & 31;
    const float* Wm = (mat == 0) ? Wq : (mat == 1) ? Wk : Wv;
    const float sc = (mat == 0) ? 1.4426950408889634f : 1.0f;
    const int e0 = ch * 64 + 2 * we;
    const float w0 = Wm[e0 * DD + d] * sc;
    const float w1 = Wm[(e0 + 1) * DD + d] * sc;
    const uint32_t h = cvt_bf2(w0, w1);
    const float r0 = w0 - __uint_as_float(h << 16);
    const float r1 = w1 - __uint_as_float(h & 0xFFFF0000u);
    g_ws[ch * 6144 + n * 32 + we]        = h;
    g_ws[ch * 6144 + 3072 + n * 32 + we] = cvt_bf2(r0, r1);
}

// ---------------------------------------------------------------------------
// HMMA projection v3: W pre-split (pure uint4 copy), x converted in-CTA.
// 64 rows/CTA -> 256 CTAs, 2 resident/SM; register-staged prefetch.
// SMEM words: XS hi @0 (64 x 36-stride), lo @2304; WT hi @4608 (96 x 36), lo @8064.
// ---------------------------------------------------------------------------
#define PXH_W 0
#define PXL_W 2304
#define PWH_W 4608
#define PWL_W 8064
#define PROJ_SMEM_BYTES (11520 * 4)

__global__ __launch_bounds__(256, 2) void proj_mma(const float* __restrict__ x)
{
    extern __shared__ uint32_t smw[];
    const int tid = threadIdx.x;
    const int wid = tid >> 5, lane = tid & 31;
    const int gid = lane >> 2, tig = lane & 3;
    const int row0 = blockIdx.x * 64;
    const int mt = wid & 3;
    const int ng = wid >> 2;
    const int mrow = mt * 16;

    // ---- W staging coordinates: 1536 uint4/chunk -> 6 per thread ----
    int w_g4[6], w_d[6];
#pragma unroll
    for (int it = 0; it < 6; it++) {
        const int u = tid + it * 256;
        const int split = (u >= 768);
        const int rem = u - split * 768;
        const int n = rem >> 3, wg = rem & 7;
        w_g4[it] = u;                                  // uint4 idx within chunk region
        w_d[it]  = (split ? PWL_W : PWH_W) + n * 36 + wg * 4;
    }
    // x-load coordinates: 64 rows x 16 float4 -> 4 per thread
    int x_r[4], x_c4[4];
#pragma unroll
    for (int it = 0; it < 4; it++) {
        const int u = tid + it * 256;
        x_r[it] = u >> 4; x_c4[it] = u & 15;
    }

    const uint4* ws4 = (const uint4*)g_ws;

    // ---- prologue: stage chunk 0 ----
    uint4 wreg[6];
    float4 xreg[4];
#pragma unroll
    for (int it = 0; it < 6; it++) wreg[it] = ws4[w_g4[it]];
#pragma unroll
    for (int it = 0; it < 4; it++)
        xreg[it] = *(const float4*)(x + (size_t)(row0 + x_r[it]) * EE + x_c4[it] * 4);

    float acc[6][4];
#pragma unroll
    for (int nt = 0; nt < 6; nt++)
#pragma unroll
        for (int j = 0; j < 4; j++) acc[nt][j] = 0.f;

    for (int ch = 0; ch < 4; ch++) {
        if (ch) __syncthreads();

        // ---- commit staged chunk ----
#pragma unroll
        for (int it = 0; it < 6; it++) *(uint4*)&smw[w_d[it]] = wreg[it];
#pragma unroll
        for (int it = 0; it < 4; it++) {
            const float4 f = xreg[it];
            const uint32_t h0 = cvt_bf2(f.x, f.y);
            const uint32_t h1 = cvt_bf2(f.z, f.w);
            const float a0 = f.x - __uint_as_float(h0 << 16);
            const float a1 = f.y - __uint_as_float(h0 & 0xFFFF0000u);
            const float a2 = f.z - __uint_as_float(h1 << 16);
            const float a3 = f.w - __uint_as_float(h1 & 0xFFFF0000u);
            const int wbase = x_r[it] * 36 + x_c4[it] * 2;
            *(uint2*)&smw[PXH_W + wbase] = make_uint2(h0, h1);
            *(uint2*)&smw[PXL_W + wbase] = make_uint2(cvt_bf2(a0, a1), cvt_bf2(a2, a3));
        }
        __syncthreads();

        // ---- prefetch next chunk ----
        if (ch + 1 < 4) {
            const int c4b = (ch + 1) * 1536;
#pragma unroll
            for (int it = 0; it < 6; it++) wreg[it] = ws4[c4b + w_g4[it]];
            const int ecn = (ch + 1) * 64;
#pragma unroll
            for (int it = 0; it < 4; it++)
                xreg[it] = *(const float4*)(x + (size_t)(row0 + x_r[it]) * EE + ecn + x_c4[it] * 4);
        }

        // ---- mma: 4 k-tiles x 6 n-tiles x 3 splits ----
#pragma unroll
        for (int kt = 0; kt < 4; kt++) {
            uint32_t ah[4], al[4];
            const int ra = (mrow + gid) * 36 + kt * 8 + tig;
            const int rb = (mrow + gid + 8) * 36 + kt * 8 + tig;
            ah[0] = smw[PXH_W + ra];     ah[1] = smw[PXH_W + rb];
            ah[2] = smw[PXH_W + ra + 4]; ah[3] = smw[PXH_W + rb + 4];
            al[0] = smw[PXL_W + ra];     al[1] = smw[PXL_W + rb];
            al[2] = smw[PXL_W + ra + 4]; al[3] = smw[PXL_W + rb + 4];
#pragma unroll
            for (int j = 0; j < 6; j++) {
                const int nt = ng * 6 + j;
                const int w0 = (nt * 8 + gid) * 36 + kt * 8 + tig;
                const uint32_t bh0 = smw[PWH_W + w0], bh1 = smw[PWH_W + w0 + 4];
                const uint32_t bl0 = smw[PWL_W + w0], bl1 = smw[PWL_W + w0 + 4];
                mma_bf16(acc[j], ah, bh0, bh1);
                mma_bf16(acc[j], ah, bl0, bl1);
                mma_bf16(acc[j], al, bh0, bh1);
            }
        }
    }

    // ---- epilogue: split + store in attn layouts ----
    const int r0 = row0 + mrow + gid, r1 = r0 + 8;
#pragma unroll
    for (int j = 0; j < 6; j++) {
        const int nt = ng * 6 + j;
        const int mat = nt >> 2;
        const int col = (nt & 3) * 8 + tig * 2;
        if (mat < 2) {
            uint32_t* dh = (uint32_t*)(mat == 0 ? g_qh : g_kh);
            uint32_t* dl = (uint32_t*)(mat == 0 ? g_ql : g_kl);
            const uint32_t h0 = cvt_bf2(acc[j][0], acc[j][1]);
            const float s00 = acc[j][0] - __uint_as_float(h0 << 16);
            const float s01 = acc[j][1] - __uint_as_float(h0 & 0xFFFF0000u);
            const uint32_t h1 = cvt_bf2(acc[j][2], acc[j][3]);
            const float s10 = acc[j][2] - __uint_as_float(h1 << 16);
            const float s11 = acc[j][3] - __uint_as_float(h1 & 0xFFFF0000u);
            const int wi0 = r0 * 16 + (col >> 1), wi1 = r1 * 16 + (col >> 1);
            dh[wi0] = h0; dl[wi0] = cvt_bf2(s00, s01);
            dh[wi1] = h1; dl[wi1] = cvt_bf2(s10, s11);
        } else {
            __nv_bfloat16* vh = (__nv_bfloat16*)g_vph;
            __nv_bfloat16* vl = (__nv_bfloat16*)g_vpl;
#pragma unroll
            for (int rr = 0; rr < 2; rr++) {
                const int r = rr ? r1 : r0;
                const int b2 = r >> 12, s = r & (SS - 1);
#pragma unroll
                for (int cc = 0; cc < 2; cc++) {
                    const float v = acc[j][rr * 2 + cc];
                    const __nv_bfloat16 hb = __float2bfloat16(v);
                    const __nv_bfloat16 lb = __float2bfloat16(v - __bfloat162float(hb));
                    const int widx = ((b2 * DD + col + cc) << 11) + (s >> 1);
                    vh[widx * 2 + (s & 1)] = hb;
                    vl[widx * 2 + (s & 1)] = lb;
                }
            }
        }
    }
}

// ---------------------------------------------------------------------------
// HMMA flash attention, split-K, ldmatrix fragment loads (R16-proven).
// ---------------------------------------------------------------------------
#define QPH_W 0
#define QPL_W 2048
#define KBASE_W 4096
#define VBASE_W 9216
#define SMEM_BYTES (14336 * 4)

__global__ __launch_bounds__(256, 2) void attn_mma()
{
    extern __shared__ uint32_t smw[];
    const int tid  = threadIdx.x;
    const int wid  = tid >> 5, lane = tid & 31;
    const int gid  = lane >> 2, tig = lane & 3;
    const int b    = blockIdx.y;
    const int q0   = blockIdx.x * 128;
    const int half = blockIdx.z;
    const int qbase = wid * 16;

    const __nv_bfloat16* khb = g_kh + (size_t)b * SS * DD;
    const __nv_bfloat16* klb = g_kl + (size_t)b * SS * DD;

#pragma unroll
    for (int it = 0; it < 4; it++) {
        const int u = tid + it * 256;
        const int split = u >> 9, r = (u >> 2) & 127, c4 = u & 3;
        const __nv_bfloat16* src = split ? g_ql : g_qh;
        const uint4 d = *(const uint4*)(src + (size_t)(b * SS + q0 + r) * DD + c4 * 8);
        *(uint4*)&smw[(split ? QPL_W : QPH_W) + r * 16 + c4 * 4] = d;
    }

    int k_off[2], k_drel[2];
    const __nv_bfloat16* k_src[2];
    int v_goff[2], v_drel[2];
    const uint32_t* v_src[2];
#pragma unroll
    for (int it = 0; it < 2; it++) {
        const int u = tid + it * 256;
        {
            const int split = u >> 8, r = (u >> 2) & 63, c4 = u & 3;
            k_src[it]  = split ? klb : khb;
            k_off[it]  = r * DD + c4 * 8;
            k_drel[it] = (split ? 1280 : 0) + r * 20 + c4 * 4;
        }
        {
            const int split = u >> 8, d = (u >> 3) & 31, k2g = u & 7;
            v_src[it]  = (split ? g_vpl : g_vph) + (size_t)b * DD * (SS / 2);
            v_goff[it] = d * (SS / 2) + k2g * 4;
            v_drel[it] = (split ? 1280 : 0) + d * 36 + k2g * 4;
        }
    }

    const uint32_t smbase = smem_u32(smw);
    const int lj = lane >> 3, lr = lane & 7;
    const uint32_t qk_lane = smbase + (uint32_t)(KBASE_W + lr * 20 + (lj & 1) * 4 + (lj >> 1) * 1280) * 4;
    const uint32_t pv_lane = smbase + (uint32_t)(VBASE_W + lr * 36 + (lj & 1) * 4 + (lj >> 1) * 1280) * 4;

    const int c0K = half * 32 * 64 * DD;
    const int c0V = half * 32 * 32;
    uint4 kreg[2], vreg[2];
#pragma unroll
    for (int it = 0; it < 2; it++) {
        kreg[it] = *(const uint4*)(k_src[it] + c0K + k_off[it]);
        vreg[it] = *(const uint4*)(v_src[it] + c0V + v_goff[it]);
    }
#pragma unroll
    for (int it = 0; it < 2; it++) {
        *(uint4*)&smw[KBASE_W + k_drel[it]] = kreg[it];
        *(uint4*)&smw[VBASE_W + v_drel[it]] = vreg[it];
    }
    __syncthreads();

    uint32_t qf[2][2][4];
#pragma unroll
    for (int s = 0; s < 2; s++)
#pragma unroll
        for (int kt = 0; kt < 2; kt++) {
            const int base = s ? QPL_W : QPH_W;
            qf[s][kt][0] = smw[base + (qbase + gid) * 16 + kt * 8 + tig];
            qf[s][kt][1] = smw[base + (qbase + gid + 8) * 16 + kt * 8 + tig];
            qf[s][kt][2] = smw[base + (qbase + gid) * 16 + kt * 8 + tig + 4];
            qf[s][kt][3] = smw[base + (qbase + gid + 8) * 16 + kt * 8 + tig + 4];
        }

    float acc[4][4];
#pragma unroll
    for (int i = 0; i < 4; i++)
#pragma unroll
        for (int j = 0; j < 4; j++) acc[i][j] = 0.f;
    float l0 = 0.f, l8 = 0.f;

    for (int nc = 0; nc < 32; nc++) {
        const int db = nc & 1;
        const bool pre = (nc + 1 < 32);

        if (pre) {
            const int kcK = c0K + (nc + 1) * 64 * DD;
            const int kcV = c0V + (nc + 1) * 32;
#pragma unroll
            for (int it = 0; it < 2; it++) {
                kreg[it] = *(const uint4*)(k_src[it] + kcK + k_off[it]);
                vreg[it] = *(const uint4*)(v_src[it] + kcV + v_goff[it]);
            }
        }

        float c[8][4];
#pragma unroll
        for (int nt = 0; nt < 8; nt++)
#pragma unroll
            for (int j = 0; j < 4; j++) c[nt][j] = 0.f;

        const uint32_t qk_db = qk_lane + (uint32_t)(db * 2560) * 4;
#pragma unroll
        for (int kt = 0; kt < 2; kt++)
#pragma unroll
            for (int nt = 0; nt < 8; nt++) {
                uint32_t kh0, kh1, kl0, kl1;
                ldsm_x4(kh0, kh1, kl0, kl1,
                        qk_db + (uint32_t)(nt * 160 + kt * 8) * 4);
                mma_bf16(c[nt], qf[0][kt], kh0, kh1);
                mma_bf16(c[nt], qf[0][kt], kl0, kl1);
                mma_bf16(c[nt], qf[1][kt], kh0, kh1);
            }

        if (pre) {
            const int o2 = (db ^ 1) * 2560;
#pragma unroll
            for (int it = 0; it < 2; it++) {
                *(uint4*)&smw[KBASE_W + o2 + k_drel[it]] = kreg[it];
                *(uint4*)&smw[VBASE_W + o2 + v_drel[it]] = vreg[it];
            }
        }

        uint32_t aph[4][4], apl[4][4];
#pragma unroll
        for (int nt = 0; nt < 8; nt++) {
            const float p0 = ex2f(c[nt][0]);
            const float p1 = ex2f(c[nt][1]);
            const float p2 = ex2f(c[nt][2]);
            const float p3 = ex2f(c[nt][3]);
            l0 += p0 + p1;
            l8 += p2 + p3;
            const uint32_t h01 = cvt_bf2(p0, p1);
            const uint32_t h23 = cvt_bf2(p2, p3);
            const float r0 = p0 - __uint_as_float(h01 << 16);
            const float r1 = p1 - __uint_as_float(h01 & 0xFFFF0000u);
            const float r2 = p2 - __uint_as_float(h23 << 16);
            const float r3 = p3 - __uint_as_float(h23 & 0xFFFF0000u);
            const uint32_t q01 = cvt_bf2(r0, r1);
            const uint32_t q23 = cvt_bf2(r2, r3);
            const int kt2 = nt >> 1, hi = (nt & 1) * 2;
            aph[kt2][hi]     = h01; aph[kt2][hi + 1] = h23;
            apl[kt2][hi]     = q01; apl[kt2][hi + 1] = q23;
        }

        const uint32_t pv_db = pv_lane + (uint32_t)(db * 2560) * 4;
#pragma unroll
        for (int kt2 = 0; kt2 < 4; kt2++)
#pragma unroll
            for (int nt2 = 0; nt2 < 4; nt2++) {
                uint32_t vh0, vh1, vl0, vl1;
                ldsm_x4(vh0, vh1, vl0, vl1,
                        pv_db + (uint32_t)(nt2 * 288 + kt2 * 8) * 4);
                mma_bf16(acc[nt2], aph[kt2], vh0, vh1);
                mma_bf16(acc[nt2], aph[kt2], vl0, vl1);
                mma_bf16(acc[nt2], apl[kt2], vh0, vh1);
            }

        __syncthreads();
    }

    l0 += __shfl_xor_sync(0xffffffffu, l0, 1, 4);
    l0 += __shfl_xor_sync(0xffffffffu, l0, 2, 4);
    l8 += __shfl_xor_sync(0xffffffffu, l8, 1, 4);
    l8 += __shfl_xor_sync(0xffffffffu, l8, 2, 4);

    const size_t row0 = (size_t)b * SS + q0 + qbase + gid;
    float* pa = g_pacc[half];
    if (tig == 0) {
        g_pl[half][row0]     = l0;
        g_pl[half][row0 + 8] = l8;
    }
#pragma unroll
    for (int nt2 = 0; nt2 < 4; nt2++) {
        *(float2*)(pa + row0 * DD + nt2 * 8 + tig * 2) =
            make_float2(acc[nt2][0], acc[nt2][1]);
        *(float2*)(pa + (row0 + 8) * DD + nt2 * 8 + tig * 2) =
            make_float2(acc[nt2][2], acc[nt2][3]);
    }
}

// ---------------------------------------------------------------------------
// Merge: out = (acc0 + acc1) * scaling / (l0 + l1).
// ---------------------------------------------------------------------------
__global__ __launch_bounds__(256, 1) void merge_kernel(float* __restrict__ out)
{
    const int i4 = blockIdx.x * 256 + threadIdx.x;
    const int row = i4 >> 3;
    const float l = g_pl[0][row] + g_pl[1][row];
    const float s = 0.17677669529663687f / l;
    const float4 a = ((const float4*)g_pacc[0])[i4];
    const float4 b = ((const float4*)g_pacc[1])[i4];
    float4 o;
    o.x = (a.x + b.x) * s; o.y = (a.y + b.y) * s;
    o.z = (a.z + b.z) * s; o.w = (a.w + b.w) * s;
    ((float4*)out)[i4] = o;
}

// ---------------------------------------------------------------------------
extern "C" void kernel_launch(void* const* d_in, const int* in_sizes, int n_in,
                              void* d_out, int out_size)
{
    const float* x  = (const float*)d_in[0];
    const float* Wq = (const float*)d_in[1];
    const float* Wk = (const float*)d_in[2];
    const float* Wv = (const float*)d_in[3];
    float* out = (float*)d_out;

    wsplit_kernel<<<48, 256>>>(Wq, Wk, Wv);

    cudaFuncSetAttribute(proj_mma, cudaFuncAttributeMaxDynamicSharedMemorySize, PROJ_SMEM_BYTES);
    proj_mma<<<(BB * SS) / 64, 256, PROJ_SMEM_BYTES>>>(x);

    cudaFuncSetAttribute(attn_mma, cudaFuncAttributeMaxDynamicSharedMemorySize, SMEM_BYTES);
    dim3 grid(SS / 128, BB, 2);
    attn_mma<<<grid, 256, SMEM_BYTES>>>();

    merge_kernel<<<(BB * SS * DD / 4) / 256, 256>>>(out);
}